// round 1
// baseline (speedup 1.0000x reference)
#include <cuda_runtime.h>

#define TT 512
#define BB 256
#define DD 256
#define HH 256
#define DH 512
#define TB (TT*BB)

// scratch (allocation-free rule: static __device__ arrays)
__device__ float g_trig[TB * 24];      // per (t,h): 12 cos(xp), 12 sin(xp)
__device__ float g_hseq[TT * HH];      // hvec per step
__device__ float g_cvec[HH];           // final cell state

__device__ __forceinline__ float fsig(float x) {
    return __fdividef(1.0f, 1.0f + __expf(-x));
}
__device__ __forceinline__ float ftanh(float x) {
    return __fmaf_rn(2.0f, __fdividef(1.0f, 1.0f + __expf(-2.0f * x)), -1.0f);
}

// ---------------------------------------------------------------------------
// Kernel A: xp[t,h,j] = sum_d W_g[q,d]*x[t,h,d] + b_g[q] + phi_g[q]
//           (j = g*3 + (q-1), q in {1,2,3}; wire 0 never used)
// store cos(xp), sin(xp) into g_trig. Warp-per-(t,h)-row, grid-stride.
// ---------------------------------------------------------------------------
__global__ void precompute_kernel(
    const float* __restrict__ x,
    const float* __restrict__ Wf, const float* __restrict__ bf, const float* __restrict__ pf,
    const float* __restrict__ Wi, const float* __restrict__ bi, const float* __restrict__ pi,
    const float* __restrict__ Wu, const float* __restrict__ bu, const float* __restrict__ pu,
    const float* __restrict__ Wo, const float* __restrict__ bo, const float* __restrict__ po)
{
    __shared__ __align__(16) float Wx[12 * 256];
    __shared__ float offs[12];

    int tid = threadIdx.x;
    // load the 12 used x-side weight rows into smem (j compile-time via unroll)
    {
        const float* Wp0 = Wf; const float* Wp1 = Wi;
        const float* Wp2 = Wu; const float* Wp3 = Wo;
#pragma unroll
        for (int j = 0; j < 12; ++j) {
            const float* Wsel = (j < 3) ? Wp0 : (j < 6) ? Wp1 : (j < 9) ? Wp2 : Wp3;
            int q = 1 + (j % 3);
            Wx[j * 256 + tid] = Wsel[q * DH + tid];
        }
    }
    if (tid < 12) {
        const float* bsel = (tid < 3) ? bf : (tid < 6) ? bi : (tid < 9) ? bu : bo;
        const float* psel = (tid < 3) ? pf : (tid < 6) ? pi : (tid < 9) ? pu : po;
        int q = 1 + (tid % 3);
        offs[tid] = bsel[q] + psel[q];
    }
    __syncthreads();

    int lane = tid & 31, warp = tid >> 5;
    const float4* x4 = (const float4*)x;
    const float4* Wx4 = (const float4*)Wx;

    for (int row = blockIdx.x * 8 + warp; row < TB; row += gridDim.x * 8) {
        float4 xa = x4[row * 64 + lane];
        float4 xb = x4[row * 64 + 32 + lane];
        float p[12];
#pragma unroll
        for (int j = 0; j < 12; ++j) {
            float4 wa = Wx4[j * 64 + lane];
            float4 wb = Wx4[j * 64 + 32 + lane];
            p[j] = xa.x * wa.x + xa.y * wa.y + xa.z * wa.z + xa.w * wa.w
                 + xb.x * wb.x + xb.y * wb.y + xb.z * wb.z + xb.w * wb.w;
        }
#pragma unroll
        for (int off = 16; off > 0; off >>= 1) {
#pragma unroll
            for (int j = 0; j < 12; ++j)
                p[j] += __shfl_xor_sync(0xffffffffu, p[j], off);
        }
        float th = 0.0f;
#pragma unroll
        for (int j = 0; j < 12; ++j)
            if (lane == j) th = p[j] + offs[j];
        if (lane < 12) {
            float s, c;
            __sincosf(th, &s, &c);
            g_trig[row * 24 + lane] = c;
            g_trig[row * 24 + 12 + lane] = s;
        }
    }
}

// ---------------------------------------------------------------------------
// Kernel B: sequential recurrence. 1 block, 384 threads (12 warps).
//   warps 0-7  : per-h gate math (h = tid), state cv in register
//   warps 0-11 : hdot[w] = W_h[w,:] @ hvec  (one warp per j), then cos/sin
// cos(xp + hd) = cos(xp)cos(hd) - sin(xp)sin(hd)
// ---------------------------------------------------------------------------
__global__ void recurrence_kernel(
    const float* __restrict__ Wf, const float* __restrict__ Wi,
    const float* __restrict__ Wu, const float* __restrict__ Wo)
{
    __shared__ __align__(16) float hv_sm[256];
    __shared__ float chs[12], shs[12];

    int tid = threadIdx.x;
    int lane = tid & 31, warp = tid >> 5;

    // reduction-warp weights: warp w lane l covers h = {4l..4l+3, 128+4l..128+4l+3}
    float4 wha, whb;
    {
        const float* Wsel = (warp < 3) ? Wf : (warp < 6) ? Wi : (warp < 9) ? Wu : Wo;
        int q = 1 + (warp % 3);
        const float4* Wr4 = (const float4*)(Wsel + q * DH + DD);  // h-part of row q
        wha = Wr4[lane];
        whb = Wr4[32 + lane];
    }

    float cv = 0.0f;
    if (tid < 12) { chs[tid] = 1.0f; shs[tid] = 0.0f; }  // hvec0 = 0 -> hdot = 0
    __syncthreads();

    const float4* trig4 = (const float4*)g_trig;
    float4 ca, cb, cc, sa, sb, sc;
    if (tid < 256) {
        int base = tid * 6;
        ca = trig4[base];     cb = trig4[base + 1]; cc = trig4[base + 2];
        sa = trig4[base + 3]; sb = trig4[base + 4]; sc = trig4[base + 5];
    }

    for (int t = 0; t < TT; ++t) {
        if (tid < 256) {
            float c0  = ca.x * chs[0]  - sa.x * shs[0];
            float c1  = ca.y * chs[1]  - sa.y * shs[1];
            float c2  = ca.z * chs[2]  - sa.z * shs[2];
            float c3  = ca.w * chs[3]  - sa.w * shs[3];
            float c4  = cb.x * chs[4]  - sb.x * shs[4];
            float c5  = cb.y * chs[5]  - sb.y * shs[5];
            float c6  = cb.z * chs[6]  - sb.z * shs[6];
            float c7  = cb.w * chs[7]  - sb.w * shs[7];
            float c8  = cc.x * chs[8]  - sc.x * shs[8];
            float c9  = cc.y * chs[9]  - sc.y * shs[9];
            float c10 = cc.z * chs[10] - sc.z * shs[10];
            float c11 = cc.w * chs[11] - sc.w * shs[11];

            float f  = fsig(c0 * c1 * c2);
            float ig = fsig(c3 * c4 * c5) * ftanh(c6 * c7 * c8);
            float o  = fsig(c9 * c10 * c11);

            cv = __fmaf_rn(f, cv, ig);
            float hx = o * ftanh(cv);
            hv_sm[tid] = hx;
            g_hseq[t * 256 + tid] = hx;       // fire-and-forget
        }
        __syncthreads();

        // prefetch next step's trig during the reduction window
        if (tid < 256 && t + 1 < TT) {
            int base = ((t + 1) * 256 + tid) * 6;
            ca = trig4[base];     cb = trig4[base + 1]; cc = trig4[base + 2];
            sa = trig4[base + 3]; sb = trig4[base + 4]; sc = trig4[base + 5];
        }

        // hdot[warp] = W_h[warp,:] @ hvec  (all 12 warps)
        {
            const float4* hv4 = (const float4*)hv_sm;
            float4 ha = hv4[lane];
            float4 hb = hv4[32 + lane];
            float s = wha.x * ha.x + wha.y * ha.y + wha.z * ha.z + wha.w * ha.w
                    + whb.x * hb.x + whb.y * hb.y + whb.z * hb.z + whb.w * hb.w;
#pragma unroll
            for (int off = 16; off > 0; off >>= 1)
                s += __shfl_xor_sync(0xffffffffu, s, off);
            if (lane == 0) chs[warp] = __cosf(s);
            if (lane == 1) shs[warp] = __sinf(s);
        }
        __syncthreads();
    }
    if (tid < 256) g_cvec[tid] = cv;
}

// ---------------------------------------------------------------------------
// Kernel C: broadcast outputs. out = [outs (T,B,H) | hx (B,H) | cx (B,H)],
// every b-row identical. Pure write bandwidth, float4.
// ---------------------------------------------------------------------------
__global__ void writeout_kernel(float4* __restrict__ out4)
{
    const int OUTS4 = TT * BB * (HH / 4);   // 8388608
    const int BH4 = BB * (HH / 4);          // 16384
    int i4 = blockIdx.x * blockDim.x + threadIdx.x;
    const float4* hs4 = (const float4*)g_hseq;
    const float4* cv4 = (const float4*)g_cvec;
    if (i4 < OUTS4) {
        int t = i4 >> 14;          // / (B*H/4)
        int h4 = i4 & 63;
        out4[i4] = hs4[t * 64 + h4];
    } else if (i4 < OUTS4 + BH4) {
        int h4 = i4 & 63;
        out4[i4] = hs4[(TT - 1) * 64 + h4];
    } else if (i4 < OUTS4 + 2 * BH4) {
        int h4 = i4 & 63;
        out4[i4] = cv4[h4];
    }
}

extern "C" void kernel_launch(void* const* d_in, const int* in_sizes, int n_in,
                              void* d_out, int out_size)
{
    const float* x  = (const float*)d_in[0];
    const float* Wf = (const float*)d_in[1];
    const float* bf = (const float*)d_in[2];
    const float* pf = (const float*)d_in[3];
    const float* Wi = (const float*)d_in[4];
    const float* bi = (const float*)d_in[5];
    const float* pi = (const float*)d_in[6];
    const float* Wu = (const float*)d_in[7];
    const float* bu = (const float*)d_in[8];
    const float* pu = (const float*)d_in[9];
    const float* Wo = (const float*)d_in[10];
    const float* bo = (const float*)d_in[11];
    const float* po = (const float*)d_in[12];

    precompute_kernel<<<592, 256>>>(x, Wf, bf, pf, Wi, bi, pi,
                                       Wu, bu, pu, Wo, bo, po);
    recurrence_kernel<<<1, 384>>>(Wf, Wi, Wu, Wo);

    const int total4 = (TT * BB * HH + 2 * BB * HH) / 4;   // 8421376
    writeout_kernel<<<(total4 + 255) / 256, 256>>>((float4*)d_out);
}

// round 3
// speedup vs baseline: 1.1156x; 1.1156x over previous
#include <cuda_runtime.h>

#define TT 512
#define BB 256
#define DD 256
#define HH 256
#define DH 512
#define TB (TT*BB)

// scratch (allocation-free rule: static __device__ arrays)
__device__ float g_trig[TB * 24];      // per (t,h): 12 cos(xp), 12 sin(xp)
__device__ float g_hseq[TT * HH];      // hvec per step
__device__ float g_cvec[HH];           // final cell state

__device__ __forceinline__ float fsig(float x) {
    return __fdividef(1.0f, 1.0f + __expf(-x));
}
__device__ __forceinline__ float ftanh(float x) {
    return __fmaf_rn(2.0f, __fdividef(1.0f, 1.0f + __expf(-2.0f * x)), -1.0f);
}

// ---------------------------------------------------------------------------
// Kernel A: xp[t,h,j] = sum_d W_g[q,d]*x[t,h,d] + b_g[q] + phi_g[q]
//           (j = g*3 + (q-1), q in {1,2,3}; wire 0 never used)
// store cos(xp), sin(xp) into g_trig. Warp-per-(t,h)-row, grid-stride.
// Two accumulator passes of 6 to keep regs <= 64 (4 blocks/SM).
// ---------------------------------------------------------------------------
__global__ __launch_bounds__(256, 4) void precompute_kernel(
    const float* __restrict__ x,
    const float* __restrict__ Wf, const float* __restrict__ bf, const float* __restrict__ pf,
    const float* __restrict__ Wi, const float* __restrict__ bi, const float* __restrict__ pi,
    const float* __restrict__ Wu, const float* __restrict__ bu, const float* __restrict__ pu,
    const float* __restrict__ Wo, const float* __restrict__ bo, const float* __restrict__ po)
{
    __shared__ __align__(16) float Wx[12 * 256];
    __shared__ float offs[12];

    int tid = threadIdx.x;
    {
#pragma unroll
        for (int j = 0; j < 12; ++j) {
            const float* Wsel = (j < 3) ? Wf : (j < 6) ? Wi : (j < 9) ? Wu : Wo;
            int q = 1 + (j % 3);
            Wx[j * 256 + tid] = Wsel[q * DH + tid];
        }
    }
    if (tid < 12) {
        const float* bsel = (tid < 3) ? bf : (tid < 6) ? bi : (tid < 9) ? bu : bo;
        const float* psel = (tid < 3) ? pf : (tid < 6) ? pi : (tid < 9) ? pu : po;
        int q = 1 + (tid % 3);
        offs[tid] = bsel[q] + psel[q];
    }
    __syncthreads();

    int lane = tid & 31, warp = tid >> 5;
    const float4* x4 = (const float4*)x;
    const float4* Wx4 = (const float4*)Wx;

    for (int row = blockIdx.x * 8 + warp; row < TB; row += gridDim.x * 8) {
        float4 xa = x4[row * 64 + lane];
        float4 xb = x4[row * 64 + 32 + lane];

        float thA, thB;
        // ---- pass 1: j = 0..5 ----
        {
            float p[6];
#pragma unroll
            for (int j = 0; j < 6; ++j) {
                float4 wa = Wx4[j * 64 + lane];
                float4 wb = Wx4[j * 64 + 32 + lane];
                p[j] = xa.x * wa.x + xa.y * wa.y + xa.z * wa.z + xa.w * wa.w
                     + xb.x * wb.x + xb.y * wb.y + xb.z * wb.z + xb.w * wb.w;
            }
#pragma unroll
            for (int off = 16; off > 0; off >>= 1)
#pragma unroll
                for (int j = 0; j < 6; ++j)
                    p[j] += __shfl_xor_sync(0xffffffffu, p[j], off);
            thA = p[0];
#pragma unroll
            for (int j = 1; j < 6; ++j)
                if (lane == j) thA = p[j];
        }
        // ---- pass 2: j = 6..11 ----
        {
            float p[6];
#pragma unroll
            for (int j = 0; j < 6; ++j) {
                float4 wa = Wx4[(j + 6) * 64 + lane];
                float4 wb = Wx4[(j + 6) * 64 + 32 + lane];
                p[j] = xa.x * wa.x + xa.y * wa.y + xa.z * wa.z + xa.w * wa.w
                     + xb.x * wb.x + xb.y * wb.y + xb.z * wb.z + xb.w * wb.w;
            }
#pragma unroll
            for (int off = 16; off > 0; off >>= 1)
#pragma unroll
                for (int j = 0; j < 6; ++j)
                    p[j] += __shfl_xor_sync(0xffffffffu, p[j], off);
            thB = p[0];
#pragma unroll
            for (int j = 1; j < 6; ++j)
                if (lane - 6 == j) thB = p[j];
        }

        if (lane < 12) {
            float th = ((lane < 6) ? thA : thB) + offs[lane];
            float s, c;
            __sincosf(th, &s, &c);
            g_trig[row * 24 + lane] = c;
            g_trig[row * 24 + 12 + lane] = s;
        }
    }
}

// ---------------------------------------------------------------------------
// Kernel B: sequential recurrence. 1 block, 384 threads (12 warps).
//   warps 0-7  : per-h gate math (h = tid), state cv in register
//   warps 0-11 : hdot[w] = W_h[w,:] @ hvec  (one warp per j), then cos/sin
// cos(xp + hd) = cos(xp)cos(hd) - sin(xp)sin(hd)
// Trig loads software-pipelined at prefetch distance 2 (A/B register sets).
// ---------------------------------------------------------------------------
__device__ __forceinline__ void lstm_step(
    int t, int pf_t, int tid, int lane, int warp,
    float4& ca, float4& cb, float4& cc, float4& sa, float4& sb, float4& sc,
    float& cv, float* hv_sm, float* chs, float* shs,
    const float4* __restrict__ trig4, float4 wha, float4 whb)
{
    if (tid < 256) {
        float c0  = ca.x * chs[0]  - sa.x * shs[0];
        float c1  = ca.y * chs[1]  - sa.y * shs[1];
        float c2  = ca.z * chs[2]  - sa.z * shs[2];
        float c3  = ca.w * chs[3]  - sa.w * shs[3];
        float c4  = cb.x * chs[4]  - sb.x * shs[4];
        float c5  = cb.y * chs[5]  - sb.y * shs[5];
        float c6  = cb.z * chs[6]  - sb.z * shs[6];
        float c7  = cb.w * chs[7]  - sb.w * shs[7];
        float c8  = cc.x * chs[8]  - sc.x * shs[8];
        float c9  = cc.y * chs[9]  - sc.y * shs[9];
        float c10 = cc.z * chs[10] - sc.z * shs[10];
        float c11 = cc.w * chs[11] - sc.w * shs[11];

        float f  = fsig(c0 * c1 * c2);
        float ig = fsig(c3 * c4 * c5) * ftanh(c6 * c7 * c8);
        float o  = fsig(c9 * c10 * c11);

        cv = __fmaf_rn(f, cv, ig);
        float hx = o * ftanh(cv);
        hv_sm[tid] = hx;
        g_hseq[t * 256 + tid] = hx;       // fire-and-forget
    }
    __syncthreads();

    // prefetch trig for step pf_t (distance 2) into the SAME register set
    if (tid < 256 && pf_t < TT) {
        int base = (pf_t * 256 + tid) * 6;
        ca = trig4[base];     cb = trig4[base + 1]; cc = trig4[base + 2];
        sa = trig4[base + 3]; sb = trig4[base + 4]; sc = trig4[base + 5];
    }

    // hdot[warp] = W_h[warp,:] @ hvec  (all 12 warps)
    {
        const float4* hv4 = (const float4*)hv_sm;
        float4 ha = hv4[lane];
        float4 hb = hv4[32 + lane];
        float s = wha.x * ha.x + wha.y * ha.y + wha.z * ha.z + wha.w * ha.w
                + whb.x * hb.x + whb.y * hb.y + whb.z * hb.z + whb.w * hb.w;
#pragma unroll
        for (int off = 16; off > 0; off >>= 1)
            s += __shfl_xor_sync(0xffffffffu, s, off);
        if (lane == 0) chs[warp] = __cosf(s);
        if (lane == 1) shs[warp] = __sinf(s);
    }
    __syncthreads();
}

__global__ __launch_bounds__(384, 1) void recurrence_kernel(
    const float* __restrict__ Wf, const float* __restrict__ Wi,
    const float* __restrict__ Wu, const float* __restrict__ Wo)
{
    __shared__ __align__(16) float hv_sm[256];
    __shared__ __align__(16) float chs[12], shs[12];

    int tid = threadIdx.x;
    int lane = tid & 31, warp = tid >> 5;

    float4 wha, whb;
    {
        const float* Wsel = (warp < 3) ? Wf : (warp < 6) ? Wi : (warp < 9) ? Wu : Wo;
        int q = 1 + (warp % 3);
        const float4* Wr4 = (const float4*)(Wsel + q * DH + DD);  // h-part of row q
        wha = Wr4[lane];
        whb = Wr4[32 + lane];
    }

    float cv = 0.0f;
    if (tid < 12) { chs[tid] = 1.0f; shs[tid] = 0.0f; }  // hvec0 = 0 -> hdot = 0
    __syncthreads();

    const float4* trig4 = (const float4*)g_trig;

    // two register buffer sets: A for even t, B for odd t
    float4 Aca, Acb, Acc, Asa, Asb, Asc;
    float4 Bca, Bcb, Bcc, Bsa, Bsb, Bsc;
    if (tid < 256) {
        int b0 = tid * 6;
        Aca = trig4[b0];     Acb = trig4[b0 + 1]; Acc = trig4[b0 + 2];
        Asa = trig4[b0 + 3]; Asb = trig4[b0 + 4]; Asc = trig4[b0 + 5];
        int b1 = (256 + tid) * 6;
        Bca = trig4[b1];     Bcb = trig4[b1 + 1]; Bcc = trig4[b1 + 2];
        Bsa = trig4[b1 + 3]; Bsb = trig4[b1 + 4]; Bsc = trig4[b1 + 5];
    }

    for (int t = 0; t < TT; t += 2) {
        lstm_step(t,     t + 2, tid, lane, warp,
                  Aca, Acb, Acc, Asa, Asb, Asc,
                  cv, hv_sm, chs, shs, trig4, wha, whb);
        lstm_step(t + 1, t + 3, tid, lane, warp,
                  Bca, Bcb, Bcc, Bsa, Bsb, Bsc,
                  cv, hv_sm, chs, shs, trig4, wha, whb);
    }
    if (tid < 256) g_cvec[tid] = cv;
}

// ---------------------------------------------------------------------------
// Kernel C: broadcast outputs. out = [outs (T,B,H) | hx (B,H) | cx (B,H)],
// every b-row identical. Pure write bandwidth, float4.
// ---------------------------------------------------------------------------
__global__ void writeout_kernel(float4* __restrict__ out4)
{
    const int OUTS4 = TT * BB * (HH / 4);   // 8388608
    const int BH4 = BB * (HH / 4);          // 16384
    int i4 = blockIdx.x * blockDim.x + threadIdx.x;
    const float4* hs4 = (const float4*)g_hseq;
    const float4* cv4 = (const float4*)g_cvec;
    if (i4 < OUTS4) {
        int t = i4 >> 14;          // / (B*H/4)
        int h4 = i4 & 63;
        out4[i4] = hs4[t * 64 + h4];
    } else if (i4 < OUTS4 + BH4) {
        int h4 = i4 & 63;
        out4[i4] = hs4[(TT - 1) * 64 + h4];
    } else if (i4 < OUTS4 + 2 * BH4) {
        int h4 = i4 & 63;
        out4[i4] = cv4[h4];
    }
}

extern "C" void kernel_launch(void* const* d_in, const int* in_sizes, int n_in,
                              void* d_out, int out_size)
{
    const float* x  = (const float*)d_in[0];
    const float* Wf = (const float*)d_in[1];
    const float* bf = (const float*)d_in[2];
    const float* pf = (const float*)d_in[3];
    const float* Wi = (const float*)d_in[4];
    const float* bi = (const float*)d_in[5];
    const float* pi = (const float*)d_in[6];
    const float* Wu = (const float*)d_in[7];
    const float* bu = (const float*)d_in[8];
    const float* pu = (const float*)d_in[9];
    const float* Wo = (const float*)d_in[10];
    const float* bo = (const float*)d_in[11];
    const float* po = (const float*)d_in[12];

    precompute_kernel<<<2368, 256>>>(x, Wf, bf, pf, Wi, bi, pi,
                                        Wu, bu, pu, Wo, bo, po);
    recurrence_kernel<<<1, 384>>>(Wf, Wi, Wu, Wo);

    const int total4 = (TT * BB * HH + 2 * BB * HH) / 4;   // 8421376
    writeout_kernel<<<(total4 + 255) / 256, 256>>>((float4*)d_out);
}

// round 5
// speedup vs baseline: 1.4822x; 1.3286x over previous
#include <cuda_runtime.h>

#define TT 512
#define BB 256
#define DD 256
#define HH 256
#define DH 512
#define TB (TT*BB)

// scratch (allocation-free rule: static __device__ arrays)
// g_trig4[(t*6 + p)*256 + h] = {cos j=2p, sin 2p, cos 2p+1, sin 2p+1} for row (t,h)
__device__ float4 g_trig4[TT * 6 * 256];
__device__ float g_hseq[TT * HH];      // hvec per step
__device__ float g_cvec[HH];           // final cell state

__device__ __forceinline__ float fsig(float x) {
    return __fdividef(1.0f, 1.0f + __expf(-x));
}
__device__ __forceinline__ float ftanh(float x) {
    return __fmaf_rn(2.0f, __fdividef(1.0f, 1.0f + __expf(-2.0f * x)), -1.0f);
}

// ---------------------------------------------------------------------------
// Kernel A: xp[t,h,j] = sum_d W_g[q,d]*x[t,h,d] + b_g[q] + phi_g[q]
// Warp-per-row; 12 used W rows in REGISTERS; tree-combined multi-reduce
// (24 useful SHFLs for 12 sums instead of 60); paired STG.128 trig store.
// Final mapping: lane holds theta_j with
//   j = (lane&2) ? 8 + b4 + 2*b3 : b4 + 2*b3 + 4*b2   (b_k = lane bit k)
// Partner (j+1, j even) value is at lane^16.
// ---------------------------------------------------------------------------
__global__ __launch_bounds__(128, 3) void precompute_kernel(
    const float* __restrict__ x,
    const float* __restrict__ Wf, const float* __restrict__ bf, const float* __restrict__ pf,
    const float* __restrict__ Wi, const float* __restrict__ bi, const float* __restrict__ pi,
    const float* __restrict__ Wu, const float* __restrict__ bu, const float* __restrict__ pu,
    const float* __restrict__ Wo, const float* __restrict__ bo, const float* __restrict__ po)
{
    int tid = threadIdx.x;
    int lane = tid & 31;
    int gwarp = (blockIdx.x * 128 + tid) >> 5;
    int nwarp = (gridDim.x * 128) >> 5;
    const unsigned FULL = 0xffffffffu;

    // hoist the 12 used weight rows into registers (lane's 8-float slice)
    float4 wa[12], wb[12];
#pragma unroll
    for (int j = 0; j < 12; ++j) {
        const float* Ws = (j < 3) ? Wf : (j < 6) ? Wi : (j < 9) ? Wu : Wo;
        int q = 1 + (j % 3);
        const float4* r4 = (const float4*)(Ws + q * DH);
        wa[j] = r4[lane];
        wb[j] = r4[32 + lane];
    }

    // per-lane j for the tree-reduce output, and its offset b[q]+phi[q]
    int b4 = (lane >> 4) & 1, b3 = (lane >> 3) & 1, b2 = (lane >> 2) & 1;
    int myj = (lane & 2) ? (8 + b4 + 2 * b3) : (b4 + 2 * b3 + 4 * b2);
    float off;
    {
        const float* bs = (myj < 3) ? bf : (myj < 6) ? bi : (myj < 9) ? bu : bo;
        const float* ps = (myj < 3) ? pf : (myj < 6) ? pi : (myj < 9) ? pu : po;
        int q = 1 + (myj % 3);
        off = bs[q] + ps[q];
    }
    bool writer = ((lane & 0x13) == 0) || ((lane & 0x17) == 2);
    int plane = myj >> 1;

    const float4* x4 = (const float4*)x;

    int row = gwarp;
    if (row >= TB) return;
    float4 xa = x4[row * 64 + lane];
    float4 xb = x4[row * 64 + 32 + lane];

    for (; row < TB; row += nwarp) {
        // prefetch next row's x
        int nrow = row + nwarp;
        float4 na, nb;
        if (nrow < TB) {
            na = x4[nrow * 64 + lane];
            nb = x4[nrow * 64 + 32 + lane];
        }

        float v[12];
#pragma unroll
        for (int j = 0; j < 12; ++j) {
            v[j] = xa.x * wa[j].x + xa.y * wa[j].y + xa.z * wa[j].z + xa.w * wa[j].w
                 + xb.x * wb[j].x + xb.y * wb[j].y + xb.z * wb[j].z + xb.w * wb[j].w;
        }

        // tree-combined multi-reduce: 12 sums in 24 shfls
#pragma unroll
        for (int j = 0; j < 12; ++j)
            v[j] += __shfl_xor_sync(FULL, v[j], 16);
        float w[6];
#pragma unroll
        for (int k = 0; k < 6; ++k) {
            w[k] = (lane & 16) ? v[2 * k + 1] : v[2 * k];
            w[k] += __shfl_xor_sync(FULL, w[k], 8);
        }
        float y[3];
#pragma unroll
        for (int m = 0; m < 3; ++m) {
            y[m] = (lane & 8) ? w[2 * m + 1] : w[2 * m];
            y[m] += __shfl_xor_sync(FULL, y[m], 4);
        }
        float z0 = (lane & 4) ? y[1] : y[0];
        float z1 = y[2];
        z0 += __shfl_xor_sync(FULL, z0, 2);
        z1 += __shfl_xor_sync(FULL, z1, 2);
        float u = (lane & 2) ? z1 : z0;
        u += __shfl_xor_sync(FULL, u, 1);

        float th = u + off;
        float s, c;
        __sincosf(th, &s, &c);
        float c1 = __shfl_xor_sync(FULL, c, 16);
        float s1 = __shfl_xor_sync(FULL, s, 16);
        if (writer) {
            int t = row >> 8, h = row & 255;
            g_trig4[(t * 6 + plane) * 256 + h] = make_float4(c, s, c1, s1);
        }

        xa = na; xb = nb;
    }
}

// ---------------------------------------------------------------------------
// Kernel B: sequential recurrence. 1 block, 384 threads (12 warps).
//   warps 0-7  : per-h gate math (h = tid), state cv in register
//   warps 0-11 : hdot[w] = W_h[w,:] @ hvec  (one warp per j), shfl butterfly
// cos(xp + hd) = cos(xp)cos(hd) - sin(xp)sin(hd)
// Trig loads coalesced (plane-major float4) + prefetch distance 2.
// ---------------------------------------------------------------------------
__device__ __forceinline__ void lstm_step(
    int t, int pf_t, int tid, int lane, int warp,
    float4& v0, float4& v1, float4& v2, float4& v3, float4& v4, float4& v5,
    float& cvr, float* hv_sm, float* chs, float* shs,
    float4 wha, float4 whb)
{
    if (tid < 256) {
        float r0  = v0.x * chs[0]  - v0.y * shs[0];
        float r1  = v0.z * chs[1]  - v0.w * shs[1];
        float r2  = v1.x * chs[2]  - v1.y * shs[2];
        float r3  = v1.z * chs[3]  - v1.w * shs[3];
        float r4  = v2.x * chs[4]  - v2.y * shs[4];
        float r5  = v2.z * chs[5]  - v2.w * shs[5];
        float r6  = v3.x * chs[6]  - v3.y * shs[6];
        float r7  = v3.z * chs[7]  - v3.w * shs[7];
        float r8  = v4.x * chs[8]  - v4.y * shs[8];
        float r9  = v4.z * chs[9]  - v4.w * shs[9];
        float r10 = v5.x * chs[10] - v5.y * shs[10];
        float r11 = v5.z * chs[11] - v5.w * shs[11];

        float f  = fsig(r0 * r1 * r2);
        float ig = fsig(r3 * r4 * r5) * ftanh(r6 * r7 * r8);
        float o  = fsig(r9 * r10 * r11);

        cvr = __fmaf_rn(f, cvr, ig);
        float hx = o * ftanh(cvr);
        hv_sm[tid] = hx;
        g_hseq[t * 256 + tid] = hx;   // fire-and-forget
    }
    __syncthreads();

    // prefetch trig for step pf_t (distance 2), fully coalesced
    if (tid < 256 && pf_t < TT) {
        const float4* tp = g_trig4 + pf_t * 6 * 256 + tid;
        v0 = tp[0];    v1 = tp[256];  v2 = tp[512];
        v3 = tp[768];  v4 = tp[1024]; v5 = tp[1280];
    }

    // hdot[warp] = W_h[warp,:] @ hvec  (all 12 warps)
    {
        const float4* hv4 = (const float4*)hv_sm;
        float4 ha = hv4[lane];
        float4 hb = hv4[32 + lane];
        float s = wha.x * ha.x + wha.y * ha.y + wha.z * ha.z + wha.w * ha.w
                + whb.x * hb.x + whb.y * hb.y + whb.z * hb.z + whb.w * hb.w;
#pragma unroll
        for (int off = 16; off > 0; off >>= 1)
            s += __shfl_xor_sync(0xffffffffu, s, off);
        if (lane == 0) {
            float sv, cw;
            __sincosf(s, &sv, &cw);
            chs[warp] = cw;
            shs[warp] = sv;
        }
    }
    __syncthreads();
}

__global__ __launch_bounds__(384, 1) void recurrence_kernel(
    const float* __restrict__ Wf, const float* __restrict__ Wi,
    const float* __restrict__ Wu, const float* __restrict__ Wo)
{
    __shared__ __align__(16) float hv_sm[256];
    __shared__ __align__(16) float chs[12];
    __shared__ __align__(16) float shs[12];

    int tid = threadIdx.x;
    int lane = tid & 31, warp = tid >> 5;

    float4 wha, whb;
    {
        const float* Wsel = (warp < 3) ? Wf : (warp < 6) ? Wi : (warp < 9) ? Wu : Wo;
        int q = 1 + (warp % 3);
        const float4* Wr4 = (const float4*)(Wsel + q * DH + DD);  // h-part of row q
        wha = Wr4[lane];
        whb = Wr4[32 + lane];
    }

    float cvr = 0.0f;
    if (tid < 12) { chs[tid] = 1.0f; shs[tid] = 0.0f; }  // hvec0 = 0 -> hdot = 0
    __syncthreads();

    // two register buffer sets: A for even t, B for odd t
    float4 A0, A1, A2, A3, A4, A5;
    float4 B0, B1, B2, B3, B4, B5;
    if (tid < 256) {
        const float4* tp0 = g_trig4 + tid;
        A0 = tp0[0];    A1 = tp0[256];  A2 = tp0[512];
        A3 = tp0[768];  A4 = tp0[1024]; A5 = tp0[1280];
        const float4* tp1 = g_trig4 + 6 * 256 + tid;
        B0 = tp1[0];    B1 = tp1[256];  B2 = tp1[512];
        B3 = tp1[768];  B4 = tp1[1024]; B5 = tp1[1280];
    }

    for (int t = 0; t < TT; t += 2) {
        lstm_step(t,     t + 2, tid, lane, warp,
                  A0, A1, A2, A3, A4, A5,
                  cvr, hv_sm, chs, shs, wha, whb);
        lstm_step(t + 1, t + 3, tid, lane, warp,
                  B0, B1, B2, B3, B4, B5,
                  cvr, hv_sm, chs, shs, wha, whb);
    }
    if (tid < 256) g_cvec[tid] = cvr;
}

// ---------------------------------------------------------------------------
// Kernel C: broadcast outputs. out = [outs (T,B,H) | hx (B,H) | cx (B,H)],
// every b-row identical. Pure write bandwidth, float4.
// ---------------------------------------------------------------------------
__global__ void writeout_kernel(float4* __restrict__ out4)
{
    const int OUTS4 = TT * BB * (HH / 4);   // 8388608
    const int BH4 = BB * (HH / 4);          // 16384
    int i4 = blockIdx.x * blockDim.x + threadIdx.x;
    const float4* hs4 = (const float4*)g_hseq;
    const float4* cv4 = (const float4*)g_cvec;
    if (i4 < OUTS4) {
        int t = i4 >> 14;          // / (B*H/4)
        int h4 = i4 & 63;
        out4[i4] = hs4[t * 64 + h4];
    } else if (i4 < OUTS4 + BH4) {
        int h4 = i4 & 63;
        out4[i4] = hs4[(TT - 1) * 64 + h4];
    } else if (i4 < OUTS4 + 2 * BH4) {
        int h4 = i4 & 63;
        out4[i4] = cv4[h4];
    }
}

extern "C" void kernel_launch(void* const* d_in, const int* in_sizes, int n_in,
                              void* d_out, int out_size)
{
    const float* x  = (const float*)d_in[0];
    const float* Wf = (const float*)d_in[1];
    const float* bf = (const float*)d_in[2];
    const float* pf = (const float*)d_in[3];
    const float* Wi = (const float*)d_in[4];
    const float* bi = (const float*)d_in[5];
    const float* pi = (const float*)d_in[6];
    const float* Wu = (const float*)d_in[7];
    const float* bu = (const float*)d_in[8];
    const float* pu = (const float*)d_in[9];
    const float* Wo = (const float*)d_in[10];
    const float* bo = (const float*)d_in[11];
    const float* po = (const float*)d_in[12];

    precompute_kernel<<<444, 128>>>(x, Wf, bf, pf, Wi, bi, pi,
                                       Wu, bu, pu, Wo, bo, po);
    recurrence_kernel<<<1, 384>>>(Wf, Wi, Wu, Wo);

    const int total4 = (TT * BB * HH + 2 * BB * HH) / 4;   // 8421376
    writeout_kernel<<<(total4 + 255) / 256, 256>>>((float4*)d_out);
}